// round 14
// baseline (speedup 1.0000x reference)
#include <cuda_runtime.h>
#include <cuda_bf16.h>

#define MW_F 1280.0f
#define MH_F 768.0f
#define HH 384
#define WW 640
#define HW (HH*WW)
#define BS 4
#define NBOX 64
#define NB (BS*NBOX)
#define SCALE_F 80.0f
#define MAXRC 104
#define MAXCELLS (MAXRC*MAXRC)
#define SPLIT 8
#define P1T 512
#define CANDMAX 2048

// Scratch (phase1a -> phase1b)
__device__ float g_vals[NB * MAXCELLS];     // ~11MB IoU scratch
__device__ float g_psum[NB * SPLIT];
__device__ int   g_pcnt[NB * SPLIT];

// Per-box results (phase1b -> phase2)
__device__ float g_thr[NB], g_cx[NB], g_cy[NB], g_bw[NB], g_bh[NB], g_score[NB], g_lam[NB];
__device__ int   g_bx[NB], g_by[NB], g_cls[NB];

struct PGeom { float mnx, mxx, mny, mxy, pw, ph; };

__device__ __forceinline__ PGeom pred_geom(float p0, float p1, float p2, float p3,
                                           float rx, float ry) {
    float x1 = __fadd_rn(__fmul_rn(p0, SCALE_F), rx);
    float y1 = __fadd_rn(__fmul_rn(p1, SCALE_F), ry);
    float x2 = __fadd_rn(__fmul_rn(p2, SCALE_F), rx);
    float y2 = __fadd_rn(__fmul_rn(p3, SCALE_F), ry);
    float w  = __fsub_rn(x2, x1);
    float h  = __fsub_rn(y2, y1);
    float cx = __fadd_rn(x1, __fmul_rn(w, 0.5f));
    float cy = __fadd_rn(y1, __fmul_rn(h, 0.5f));
    PGeom g;
    g.mnx = __fsub_rn(cx, __fmul_rn(w, 0.5f));
    g.mxx = __fadd_rn(cx, __fmul_rn(w, 0.5f));
    g.mny = __fsub_rn(cy, __fmul_rn(h, 0.5f));
    g.mxy = __fadd_rn(cy, __fmul_rn(h, 0.5f));
    g.pw = w; g.ph = h;
    return g;
}

__device__ __forceinline__ float iou_fn(const PGeom& g, float cx, float cy,
                                        float bw, float bh) {
    float gmnx = __fsub_rn(cx, __fmul_rn(bw, 0.5f));
    float gmxx = __fadd_rn(cx, __fmul_rn(bw, 0.5f));
    float gmny = __fsub_rn(cy, __fmul_rn(bh, 0.5f));
    float gmxy = __fadd_rn(cy, __fmul_rn(bh, 0.5f));
    float iw = fmaxf(__fsub_rn(fminf(g.mxx, gmxx), fmaxf(g.mnx, gmnx)), 0.0f);
    float ih = fmaxf(__fsub_rn(fminf(g.mxy, gmxy), fmaxf(g.mny, gmny)), 0.0f);
    float inter = __fmul_rn(iw, ih);
    float uni = __fsub_rn(__fadd_rn(__fmul_rn(g.pw, g.ph), __fmul_rn(bw, bh)), inter);
    return __fdiv_rn(inter, fmaxf(uni, 1e-6f));
}

// Box geometry shared by all phase-1 kernels (pinned ops, identical everywhere)
struct BoxInfo {
    float cx, cy, bw, bh, clsf, diff;
    int ix0, ix1, iy0, iy1, rw, rh, cnt, nq, qa0;
    int Q;
    bool empty;
};

__device__ __forceinline__ BoxInfo box_info(const float* __restrict__ bboxes, int bn) {
    BoxInfo bi;
    const float* bx = bboxes + bn * 6;
    float x1 = bx[0], y1 = bx[1], x2 = bx[2], y2 = bx[3];
    bi.clsf = bx[4]; bi.diff = bx[5];
    bi.bw = __fsub_rn(x2, x1);
    bi.bh = __fsub_rn(y2, y1);
    bi.cx = __fadd_rn(x1, __fmul_rn(bi.bw, 0.5f));
    bi.cy = __fadd_rn(y1, __fmul_rn(bi.bh, 0.5f));
    bool valid = (__fmul_rn(bi.bw, bi.bh) != 0.0f);
    float mnw = floorf(fmaxf(__fsub_rn(__fdiv_rn(__fmul_rn(x1, (float)WW), MW_F), 0.5f), 0.0f));
    float mnh = floorf(fmaxf(__fsub_rn(__fdiv_rn(__fmul_rn(y1, (float)HH), MH_F), 0.5f), 0.0f));
    float mxw = ceilf (fminf(__fsub_rn(__fdiv_rn(__fmul_rn(x2, (float)WW), MW_F), 0.5f), (float)(WW - 1)));
    float mxh = ceilf (fminf(__fsub_rn(__fdiv_rn(__fmul_rn(y2, (float)HH), MH_F), 0.5f), (float)(HH - 1)));
    bi.ix0 = (int)mnw; bi.ix1 = (int)mxw; bi.iy0 = (int)mnh; bi.iy1 = (int)mxh;
    bi.empty = (!valid) || (bi.ix1 < bi.ix0) || (bi.iy1 < bi.iy0);
    bi.rw = bi.empty ? 0 : (bi.ix1 - bi.ix0 + 1);
    bi.rh = bi.empty ? 0 : (bi.iy1 - bi.iy0 + 1);
    bi.cnt = bi.rw * bi.rh;
    if (bi.cnt > MAXCELLS) bi.cnt = MAXCELLS;
    bi.qa0 = bi.ix0 >> 2;
    int qa1 = bi.ix1 >> 2;
    bi.nq = bi.empty ? 0 : (qa1 - bi.qa0 + 1);
    bi.Q = bi.rh * bi.nq;
    return bi;
}

// Warp-0-only locate: find bin B with suffix(bins>B) <= want < suffix+hist[B].
__device__ __forceinline__ void locate_warp(const unsigned* hist, int nbins,
                                            int want, int lane,
                                            int* s_bin, int* s_wrem) {
    const int chunk = nbins >> 5;
    const int base = lane * chunk;
    unsigned partial = 0;
    #pragma unroll 8
    for (int k = 0; k < chunk; k++) partial += hist[base + k];
    unsigned suf = partial;
    #pragma unroll
    for (int s = 1; s < 32; s <<= 1) {
        unsigned v = __shfl_down_sync(0xFFFFFFFFu, suf, s);
        if (lane + s < 32) suf += v;
    }
    unsigned running = suf - partial;
    for (int k = chunk - 1; k >= 0; k--) {
        unsigned h = hist[base + k];
        if ((unsigned)want >= running && (unsigned)want < running + h) {
            *s_bin = base + k;
            *s_wrem = (int)((unsigned)want - running);
        }
        running += h;
    }
}

// ---------------- Phase 1a: IoU compute, split SPLIT-ways per box ----------------
__global__ __launch_bounds__(P1T) void phase1a_kernel(
    const float* __restrict__ pred,    // [BS,4,H,W]
    const float* __restrict__ bboxes)  // [BS,NBOX,6]
{
    __shared__ float s_wsum[16];
    __shared__ int   s_wcnt[16];

    const int bn = blockIdx.x;
    const int s  = blockIdx.y;
    const int b  = bn / NBOX;
    const int tid = threadIdx.x;
    const int lane = tid & 31;
    const int wid = tid >> 5;

    BoxInfo bi = box_info(bboxes, bn);

    int chunkQ = (bi.Q + SPLIT - 1) / SPLIT;
    int qs = s * chunkQ;
    int qe = min(qs + chunkQ, bi.Q);

    unsigned invq = (bi.nq > 0) ? (((1u << 22) + (unsigned)bi.nq - 1u) / (unsigned)bi.nq) : 1u;

    float psum = 0.0f;
    int pcount = 0;
    const float* pbase = pred + (b * 4) * HW;
    float* vbase = g_vals + bn * MAXCELLS;

    for (int q = qs + tid; q < qe; q += P1T) {
        int ri = (int)((unsigned)(((unsigned long long)(unsigned)q * invq) >> 22));
        int qq = q - ri * bi.nq;
        int i = bi.iy0 + ri;
        int jb = (bi.qa0 + qq) << 2;
        const float* pb = pbase + i * WW + jb;
        float4 r0 = *(const float4*)(pb);
        float4 r1 = *(const float4*)(pb + HW);
        float4 r2 = *(const float4*)(pb + 2 * HW);
        float4 r3 = *(const float4*)(pb + 3 * HW);
        float a0[4] = {r0.x, r0.y, r0.z, r0.w};
        float a1[4] = {r1.x, r1.y, r1.z, r1.w};
        float a2[4] = {r2.x, r2.y, r2.z, r2.w};
        float a3[4] = {r3.x, r3.y, r3.z, r3.w};
        float ry = __fmul_rn(__fadd_rn((float)i, 0.5f), 2.0f);
        int cbase = ri * bi.rw + (jb - bi.ix0);
        #pragma unroll
        for (int u = 0; u < 4; u++) {
            int j = jb + u;
            if (j >= bi.ix0 && j <= bi.ix1) {
                float rx = __fmul_rn(__fadd_rn((float)j, 0.5f), 2.0f);
                PGeom g = pred_geom(a0[u], a1[u], a2[u], a3[u], rx, ry);
                float v = iou_fn(g, bi.cx, bi.cy, bi.bw, bi.bh);
                vbase[cbase + u] = v;
                if (v > 0.0f) { psum += v; pcount++; }
            }
        }
    }

    // deterministic block reduction (fixed warp order)
    #pragma unroll
    for (int off = 16; off > 0; off >>= 1) {
        psum += __shfl_down_sync(0xFFFFFFFFu, psum, off);
        pcount += __shfl_down_sync(0xFFFFFFFFu, pcount, off);
    }
    if (lane == 0) { s_wsum[wid] = psum; s_wcnt[wid] = pcount; }
    __syncthreads();
    if (tid == 0) {
        float t = 0.0f; int p = 0;
        #pragma unroll
        for (int w = 0; w < 16; w++) { t += s_wsum[w]; p += s_wcnt[w]; }
        g_psum[bn * SPLIT + s] = t;
        g_pcnt[bn * SPLIT + s] = p;
    }
}

// ---------------- Phase 1b: exact rank-dk threshold from scratch values ----------------
__global__ __launch_bounds__(P1T) void phase1b_kernel(
    const float* __restrict__ bboxes,
    const int*   __restrict__ dmode)
{
    __shared__ unsigned hist[2048];
    __shared__ unsigned cand[CANDMAX];
    __shared__ int s_dk, s_P, s_bin, s_wrem, s_m;

    const int bn = blockIdx.x;
    const int tid = threadIdx.x;
    const int lane = tid & 31;
    const int wid = tid >> 5;

    BoxInfo bi = box_info(bboxes, bn);
    const float* vbase = g_vals + bn * MAXCELLS;
    const int cnt = bi.cnt;

    if (tid == 0) {
        float t = 0.0f; int p = 0;
        #pragma unroll
        for (int k = 0; k < SPLIT; k++) { t += g_psum[bn * SPLIT + k]; p += g_pcnt[bn * SPLIT + k]; }
        float dkf = ceilf(fmaxf(t, 1.0f));
        if (!(dkf < (float)(HW - 1))) dkf = (float)(HW - 1);
        s_dk = (int)dkf;
        s_P = p;
        s_m = 0;
    }
    __syncthreads();

    const int dk = s_dk;
    const int P = s_P;
    float thr = 0.0f;

    if (dk < P) {
        // level 1: bits [31:21]
        #pragma unroll
        for (int h = tid; h < 2048; h += P1T) hist[h] = 0;
        __syncthreads();
        for (int c = tid; c < cnt; c += P1T) {
            float v = vbase[c];
            if (v > 0.0f) atomicAdd(&hist[__float_as_uint(v) >> 21], 1u);
        }
        __syncthreads();
        if (wid == 0) locate_warp(hist, 2048, dk, lane, &s_bin, &s_wrem);
        __syncthreads();
        const int b1 = s_bin, want2 = s_wrem;
        const int m = (int)hist[b1];
        __syncthreads();

        int b2, b3, want3;
        if (m <= CANDMAX) {
            // gather candidates of bin b1 (order irrelevant: used as multiset)
            for (int c = tid; c < cnt; c += P1T) {
                float v = vbase[c];
                unsigned u = __float_as_uint(v);
                if (v > 0.0f && (int)(u >> 21) == b1) {
                    int pos = atomicAdd(&s_m, 1);
                    cand[pos] = u;
                }
            }
            __syncthreads();
            // level 2 on candidates: bits [20:10]
            #pragma unroll
            for (int h = tid; h < 2048; h += P1T) hist[h] = 0;
            __syncthreads();
            for (int k = tid; k < m; k += P1T)
                atomicAdd(&hist[(cand[k] >> 10) & 0x7FFu], 1u);
            __syncthreads();
            if (wid == 0) locate_warp(hist, 2048, want2, lane, &s_bin, &s_wrem);
            __syncthreads();
            b2 = s_bin; want3 = s_wrem;
            __syncthreads();
            // level 3 on candidates: bits [9:0]
            #pragma unroll
            for (int h = tid; h < 1024; h += P1T) hist[h] = 0;
            __syncthreads();
            for (int k = tid; k < m; k += P1T)
                if ((int)((cand[k] >> 10) & 0x7FFu) == b2)
                    atomicAdd(&hist[cand[k] & 0x3FFu], 1u);
            __syncthreads();
            if (wid == 0) locate_warp(hist, 1024, want3, lane, &s_bin, &s_wrem);
            __syncthreads();
            b3 = s_bin;
        } else {
            // rare fallback: full scans for levels 2 and 3 (exact)
            #pragma unroll
            for (int h = tid; h < 2048; h += P1T) hist[h] = 0;
            __syncthreads();
            for (int c = tid; c < cnt; c += P1T) {
                float v = vbase[c];
                unsigned u = __float_as_uint(v);
                if (v > 0.0f && (int)(u >> 21) == b1)
                    atomicAdd(&hist[(u >> 10) & 0x7FFu], 1u);
            }
            __syncthreads();
            if (wid == 0) locate_warp(hist, 2048, want2, lane, &s_bin, &s_wrem);
            __syncthreads();
            b2 = s_bin; want3 = s_wrem;
            __syncthreads();
            unsigned pref21 = ((unsigned)b1 << 11) | (unsigned)b2;
            #pragma unroll
            for (int h = tid; h < 1024; h += P1T) hist[h] = 0;
            __syncthreads();
            for (int c = tid; c < cnt; c += P1T) {
                float v = vbase[c];
                unsigned u = __float_as_uint(v);
                if (v > 0.0f && (u >> 10) == pref21)
                    atomicAdd(&hist[u & 0x3FFu], 1u);
            }
            __syncthreads();
            if (wid == 0) locate_warp(hist, 1024, want3, lane, &s_bin, &s_wrem);
            __syncthreads();
            b3 = s_bin;
        }
        thr = __uint_as_float(((unsigned)b1 << 21) | ((unsigned)b2 << 10) | (unsigned)b3);
    }

    if (tid == 0) {
        g_thr[bn] = thr;
        g_cx[bn] = bi.cx; g_cy[bn] = bi.cy; g_bw[bn] = bi.bw; g_bh[bn] = bi.bh;
        int dm = *dmode;
        g_score[bn] = dm ? ((bi.diff >= 0.625f) ? 1.0f : 0.0f) : 1.0f;
        g_lam[bn] = 1.0f / sqrtf((float)dk);
        g_cls[bn] = (int)bi.clsf + 1;
        if (bi.empty) { g_bx[bn] = 0xFFFF; g_by[bn] = 0xFFFF; }
        else          { g_bx[bn] = bi.ix0 | (bi.ix1 << 16); g_by[bn] = bi.iy0 | (bi.iy1 << 16); }
    }
}

// ---------------- Phase 2: per-pixel argmax/tie across boxes + outputs ----------------
__global__ __launch_bounds__(256) void phase2_kernel(
    const float* __restrict__ pred,  // [BS,4,H,W]
    float* __restrict__ out)         // cls [BS,H,W,3] then pts [BS,H,W,6]
{
    __shared__ unsigned s_mask[2];
    __shared__ int   s_ncand;
    __shared__ int   s_bxp[NBOX], s_byp[NBOX], s_clsid[NBOX];
    __shared__ float s_thr[NBOX], s_cx[NBOX], s_cy[NBOX], s_bw[NBOX], s_bh[NBOX];
    __shared__ float s_sc[NBOX], s_lm[NBOX];

    const int b = blockIdx.z;
    const int j0 = blockIdx.x * 64;
    const int i0 = blockIdx.y * 4;
    const int tid = threadIdx.x;

    bool f = false;
    int bxp = 0, byp = 0;
    if (tid < NBOX) {
        int idx = b * NBOX + tid;
        bxp = g_bx[idx]; byp = g_by[idx];
        int x0 = bxp & 0xFFFF, x1 = bxp >> 16;
        int y0 = byp & 0xFFFF, y1 = byp >> 16;
        f = (x0 <= j0 + 63) && (x1 >= j0) && (y0 <= i0 + 3) && (y1 >= i0);
    }
    unsigned m = __ballot_sync(0xFFFFFFFFu, f);
    if (tid < NBOX && (tid & 31) == 0) s_mask[tid >> 5] = m;
    __syncthreads();
    int base0 = __popc(s_mask[0]);
    if (tid == 0) s_ncand = base0 + __popc(s_mask[1]);
    if (f) {
        int lane = tid & 31;
        int pos = ((tid >> 5) ? base0 : 0) + __popc(m & ((1u << lane) - 1u));
        int idx = b * NBOX + tid;
        s_bxp[pos] = bxp; s_byp[pos] = byp;
        s_thr[pos] = g_thr[idx];
        s_cx[pos] = g_cx[idx]; s_cy[pos] = g_cy[idx];
        s_bw[pos] = g_bw[idx]; s_bh[pos] = g_bh[idx];
        s_sc[pos] = g_score[idx]; s_lm[pos] = g_lam[idx];
        s_clsid[pos] = g_cls[idx];
    }
    __syncthreads();

    const int j = j0 + (tid & 63);
    const int i = i0 + (tid >> 6);
    const int pix = i * WW + j;

    const float* pb = pred + (b * 4) * HW + pix;
    float p0 = pb[0 * HW], p1 = pb[1 * HW], p2 = pb[2 * HW], p3 = pb[3 * HW];
    float rx = __fmul_rn(__fadd_rn((float)j, 0.5f), 2.0f);
    float ry = __fmul_rn(__fadd_rn((float)i, 0.5f), 2.0f);
    PGeom g = pred_geom(p0, p1, p2, p3, rx, ry);

    float best = 0.0f;
    int win = 0;
    int cntmax = 0;
    bool inreg = false;
    const int nc = s_ncand;
    for (int k = 0; k < nc; k++) {
        int bp = s_bxp[k], yp = s_byp[k];
        if (j >= (bp & 0xFFFF) && j <= (bp >> 16) &&
            i >= (yp & 0xFFFF) && i <= (yp >> 16)) {
            inreg = true;
            float iou = iou_fn(g, s_cx[k], s_cy[k], s_bw[k], s_bh[k]);
            float kept = (iou > s_thr[k]) ? iou : 0.0f;
            if (kept > best) { best = kept; win = k; cntmax = 1; }
            else if (kept == best && kept > 0.0f) cntmax++;
        }
    }

    bool assigned = (best > 0.0f);
    float c0, c1, c2;
    if (assigned) {
        if (cntmax > 1) { c0 = c1 = c2 = 0.0f; }
        else {
            int ci = s_clsid[win];
            c0 = (ci == 0) ? 1.0f : 0.0f;
            c1 = (ci == 1) ? 1.0f : 0.0f;
            c2 = (ci == 2) ? 1.0f : 0.0f;
        }
    } else if (inreg) {
        c0 = c1 = c2 = 0.0f;
    } else {
        c0 = 1.0f; c1 = 0.0f; c2 = 0.0f;
    }
    int cidx = (b * HW + pix) * 3;
    out[cidx + 0] = c0; out[cidx + 1] = c1; out[cidx + 2] = c2;

    int pidx = BS * HW * 3 + (b * HW + pix) * 6;
    float2* pv = reinterpret_cast<float2*>(out + pidx);
    if (assigned) {
        pv[0] = make_float2(s_cx[win], s_cy[win]);
        pv[1] = make_float2(s_bw[win], s_bh[win]);
        pv[2] = make_float2(s_sc[win], s_lm[win]);
    } else {
        pv[0] = make_float2(1.0f, 1.0f);
        pv[1] = make_float2(1.0f, 1.0f);
        pv[2] = make_float2(1.0f, 1.0f);
    }
}

extern "C" void kernel_launch(void* const* d_in, const int* in_sizes, int n_in,
                              void* d_out, int out_size) {
    // inputs: [0]=feat (unused), [1]=pred, [2]=bboxes, [3]=difficult_mode (int32)
    const float* pred   = (const float*)d_in[1];
    const float* bboxes = (const float*)d_in[2];
    const int*   dmode  = (const int*)d_in[3];
    float* out = (float*)d_out;

    dim3 g1a(NB, SPLIT);
    phase1a_kernel<<<g1a, P1T>>>(pred, bboxes);
    phase1b_kernel<<<NB, P1T>>>(bboxes, dmode);
    dim3 g2(WW / 64, HH / 4, BS);
    phase2_kernel<<<g2, 256>>>(pred, out);
}

// round 15
// speedup vs baseline: 1.1147x; 1.1147x over previous
#include <cuda_runtime.h>
#include <cuda_bf16.h>

#define MW_F 1280.0f
#define MH_F 768.0f
#define HH 384
#define WW 640
#define HW (HH*WW)
#define BS 4
#define NBOX 64
#define NB (BS*NBOX)
#define SCALE_F 80.0f
#define MAXRC 104
#define MAXCELLS (MAXRC*MAXRC)
#define SPLIT 8
#define P1AT 256
#define P1BT 256
#define CANDMAX 2048

// Scratch (phase1a -> phase1b)
__device__ float g_vals[NB * MAXCELLS];     // ~11MB IoU scratch
__device__ float g_psum[NB * SPLIT];
__device__ int   g_pcnt[NB * SPLIT];

// Per-box params (phase0 -> phase1a/1b) and results (-> phase2)
__device__ float g_thr[NB], g_cx[NB], g_cy[NB], g_bw[NB], g_bh[NB], g_score[NB], g_lam[NB];
__device__ int   g_bx[NB], g_by[NB], g_cls[NB];
__device__ int   g_iy0[NB], g_rw[NB], g_nq[NB], g_qa0[NB], g_Q[NB], g_cnt[NB];
__device__ unsigned g_invq[NB];

struct PGeom { float mnx, mxx, mny, mxy, pw, ph; };

__device__ __forceinline__ PGeom pred_geom(float p0, float p1, float p2, float p3,
                                           float rx, float ry) {
    float x1 = __fadd_rn(__fmul_rn(p0, SCALE_F), rx);
    float y1 = __fadd_rn(__fmul_rn(p1, SCALE_F), ry);
    float x2 = __fadd_rn(__fmul_rn(p2, SCALE_F), rx);
    float y2 = __fadd_rn(__fmul_rn(p3, SCALE_F), ry);
    float w  = __fsub_rn(x2, x1);
    float h  = __fsub_rn(y2, y1);
    float cx = __fadd_rn(x1, __fmul_rn(w, 0.5f));
    float cy = __fadd_rn(y1, __fmul_rn(h, 0.5f));
    PGeom g;
    g.mnx = __fsub_rn(cx, __fmul_rn(w, 0.5f));
    g.mxx = __fadd_rn(cx, __fmul_rn(w, 0.5f));
    g.mny = __fsub_rn(cy, __fmul_rn(h, 0.5f));
    g.mxy = __fadd_rn(cy, __fmul_rn(h, 0.5f));
    g.pw = w; g.ph = h;
    return g;
}

__device__ __forceinline__ float iou_fn(const PGeom& g, float cx, float cy,
                                        float bw, float bh) {
    float gmnx = __fsub_rn(cx, __fmul_rn(bw, 0.5f));
    float gmxx = __fadd_rn(cx, __fmul_rn(bw, 0.5f));
    float gmny = __fsub_rn(cy, __fmul_rn(bh, 0.5f));
    float gmxy = __fadd_rn(cy, __fmul_rn(bh, 0.5f));
    float iw = fmaxf(__fsub_rn(fminf(g.mxx, gmxx), fmaxf(g.mnx, gmnx)), 0.0f);
    float ih = fmaxf(__fsub_rn(fminf(g.mxy, gmxy), fmaxf(g.mny, gmny)), 0.0f);
    float inter = __fmul_rn(iw, ih);
    float uni = __fsub_rn(__fadd_rn(__fmul_rn(g.pw, g.ph), __fmul_rn(bw, bh)), inter);
    return __fdiv_rn(inter, fmaxf(uni, 1e-6f));
}

// ---------------- Phase 0: per-box geometry, computed once ----------------
__global__ __launch_bounds__(NB) void phase0_kernel(
    const float* __restrict__ bboxes,  // [BS,NBOX,6]
    const int*   __restrict__ dmode)
{
    const int bn = threadIdx.x;
    const float* bx = bboxes + bn * 6;
    float x1 = bx[0], y1 = bx[1], x2 = bx[2], y2 = bx[3], clsf = bx[4], diff = bx[5];
    float bw = __fsub_rn(x2, x1);
    float bh = __fsub_rn(y2, y1);
    float cx = __fadd_rn(x1, __fmul_rn(bw, 0.5f));
    float cy = __fadd_rn(y1, __fmul_rn(bh, 0.5f));
    bool valid = (__fmul_rn(bw, bh) != 0.0f);

    float mnw = floorf(fmaxf(__fsub_rn(__fdiv_rn(__fmul_rn(x1, (float)WW), MW_F), 0.5f), 0.0f));
    float mnh = floorf(fmaxf(__fsub_rn(__fdiv_rn(__fmul_rn(y1, (float)HH), MH_F), 0.5f), 0.0f));
    float mxw = ceilf (fminf(__fsub_rn(__fdiv_rn(__fmul_rn(x2, (float)WW), MW_F), 0.5f), (float)(WW - 1)));
    float mxh = ceilf (fminf(__fsub_rn(__fdiv_rn(__fmul_rn(y2, (float)HH), MH_F), 0.5f), (float)(HH - 1)));
    int ix0 = (int)mnw, ix1 = (int)mxw, iy0 = (int)mnh, iy1 = (int)mxh;
    bool empty = (!valid) || (ix1 < ix0) || (iy1 < iy0);
    int rw = empty ? 0 : (ix1 - ix0 + 1);
    int rh = empty ? 0 : (iy1 - iy0 + 1);
    int cnt = rw * rh;
    if (cnt > MAXCELLS) cnt = MAXCELLS;
    int qa0 = ix0 >> 2, qa1 = ix1 >> 2;
    int nq = empty ? 0 : (qa1 - qa0 + 1);
    int Q = rh * nq;

    g_cx[bn] = cx; g_cy[bn] = cy; g_bw[bn] = bw; g_bh[bn] = bh;
    g_cls[bn] = (int)clsf + 1;
    int dm = *dmode;
    g_score[bn] = dm ? ((diff >= 0.625f) ? 1.0f : 0.0f) : 1.0f;
    g_iy0[bn] = iy0; g_rw[bn] = rw; g_nq[bn] = nq; g_qa0[bn] = qa0;
    g_Q[bn] = Q; g_cnt[bn] = cnt;
    g_invq[bn] = (nq > 0) ? (((1u << 22) + (unsigned)nq - 1u) / (unsigned)nq) : 1u;
    if (empty) { g_bx[bn] = 0xFFFF; g_by[bn] = 0xFFFF; }
    else       { g_bx[bn] = ix0 | (ix1 << 16); g_by[bn] = iy0 | (iy1 << 16); }
}

// ---------------- Phase 1a: IoU compute, SPLIT sub-blocks per box ----------------
__global__ __launch_bounds__(P1AT) void phase1a_kernel(
    const float* __restrict__ pred)    // [BS,4,H,W]
{
    __shared__ float s_wsum[8];
    __shared__ int   s_wcnt[8];

    const int bn = blockIdx.x;
    const int s  = blockIdx.y;
    const int b  = bn >> 6;
    const int tid = threadIdx.x;
    const int lane = tid & 31;
    const int wid = tid >> 5;

    const int Q = g_Q[bn];
    const int nq = g_nq[bn];
    const int iy0 = g_iy0[bn];
    const int rw = g_rw[bn];
    const int qa0 = g_qa0[bn];
    const unsigned invq = g_invq[bn];
    const int packed = g_bx[bn];
    const int ix0 = packed & 0xFFFF, ix1 = packed >> 16;
    const float cx = g_cx[bn], cy = g_cy[bn], bw = g_bw[bn], bh = g_bh[bn];

    int chunkQ = (Q + SPLIT - 1) / SPLIT;
    int qs = s * chunkQ;
    int qe = min(qs + chunkQ, Q);

    float psum = 0.0f;
    int pcount = 0;
    const float* pbase = pred + (b * 4) * HW;
    float* vbase = g_vals + bn * MAXCELLS;

    for (int q = qs + tid; q < qe; q += P1AT) {
        int ri = (int)((unsigned)(((unsigned long long)(unsigned)q * invq) >> 22));
        int qq = q - ri * nq;
        int i = iy0 + ri;
        int jb = (qa0 + qq) << 2;
        const float* pb = pbase + i * WW + jb;
        float4 r0 = *(const float4*)(pb);
        float4 r1 = *(const float4*)(pb + HW);
        float4 r2 = *(const float4*)(pb + 2 * HW);
        float4 r3 = *(const float4*)(pb + 3 * HW);
        float a0[4] = {r0.x, r0.y, r0.z, r0.w};
        float a1[4] = {r1.x, r1.y, r1.z, r1.w};
        float a2[4] = {r2.x, r2.y, r2.z, r2.w};
        float a3[4] = {r3.x, r3.y, r3.z, r3.w};
        float ry = __fmul_rn(__fadd_rn((float)i, 0.5f), 2.0f);
        int cbase = ri * rw + (jb - ix0);
        #pragma unroll
        for (int u = 0; u < 4; u++) {
            int j = jb + u;
            if (j >= ix0 && j <= ix1) {
                float rx = __fmul_rn(__fadd_rn((float)j, 0.5f), 2.0f);
                PGeom g = pred_geom(a0[u], a1[u], a2[u], a3[u], rx, ry);
                float v = iou_fn(g, cx, cy, bw, bh);
                vbase[cbase + u] = v;
                if (v > 0.0f) { psum += v; pcount++; }
            }
        }
    }

    // deterministic block reduction (fixed warp order)
    #pragma unroll
    for (int off = 16; off > 0; off >>= 1) {
        psum += __shfl_down_sync(0xFFFFFFFFu, psum, off);
        pcount += __shfl_down_sync(0xFFFFFFFFu, pcount, off);
    }
    if (lane == 0) { s_wsum[wid] = psum; s_wcnt[wid] = pcount; }
    __syncthreads();
    if (tid == 0) {
        float t = 0.0f; int p = 0;
        #pragma unroll
        for (int w = 0; w < 8; w++) { t += s_wsum[w]; p += s_wcnt[w]; }
        g_psum[bn * SPLIT + s] = t;
        g_pcnt[bn * SPLIT + s] = p;
    }
}

// Warp-0-only locate: find bin B with suffix(bins>B) <= want < suffix+hist[B].
__device__ __forceinline__ void locate_warp(const unsigned* hist, int nbins,
                                            int want, int lane,
                                            int* s_bin, int* s_wrem) {
    const int chunk = nbins >> 5;
    const int base = lane * chunk;
    unsigned partial = 0;
    #pragma unroll 8
    for (int k = 0; k < chunk; k++) partial += hist[base + k];
    unsigned suf = partial;
    #pragma unroll
    for (int s = 1; s < 32; s <<= 1) {
        unsigned v = __shfl_down_sync(0xFFFFFFFFu, suf, s);
        if (lane + s < 32) suf += v;
    }
    unsigned running = suf - partial;
    for (int k = chunk - 1; k >= 0; k--) {
        unsigned h = hist[base + k];
        if ((unsigned)want >= running && (unsigned)want < running + h) {
            *s_bin = base + k;
            *s_wrem = (int)((unsigned)want - running);
        }
        running += h;
    }
}

// ---------------- Phase 1b: exact rank-dk threshold from scratch values ----------------
__global__ __launch_bounds__(P1BT) void phase1b_kernel()
{
    __shared__ unsigned hist[2048];
    __shared__ unsigned cand[CANDMAX];
    __shared__ int s_dk, s_P, s_bin, s_wrem, s_m;

    const int bn = blockIdx.x;
    const int tid = threadIdx.x;
    const int lane = tid & 31;
    const int wid = tid >> 5;

    const float* vbase = g_vals + bn * MAXCELLS;
    const int cnt = g_cnt[bn];

    if (tid == 0) {
        float t = 0.0f; int p = 0;
        #pragma unroll
        for (int k = 0; k < SPLIT; k++) { t += g_psum[bn * SPLIT + k]; p += g_pcnt[bn * SPLIT + k]; }
        float dkf = ceilf(fmaxf(t, 1.0f));
        if (!(dkf < (float)(HW - 1))) dkf = (float)(HW - 1);
        s_dk = (int)dkf;
        s_P = p;
        s_m = 0;
    }
    __syncthreads();

    const int dk = s_dk;
    const int P = s_P;
    float thr = 0.0f;

    if (dk < P) {
        // level 1: bits [31:21]
        #pragma unroll
        for (int h = tid; h < 2048; h += P1BT) hist[h] = 0;
        __syncthreads();
        for (int c = tid; c < cnt; c += P1BT) {
            float v = vbase[c];
            if (v > 0.0f) atomicAdd(&hist[__float_as_uint(v) >> 21], 1u);
        }
        __syncthreads();
        if (wid == 0) locate_warp(hist, 2048, dk, lane, &s_bin, &s_wrem);
        __syncthreads();
        const int b1 = s_bin, want2 = s_wrem;
        const int m = (int)hist[b1];
        __syncthreads();

        int b2, b3, want3;
        if (m <= CANDMAX) {
            for (int c = tid; c < cnt; c += P1BT) {
                float v = vbase[c];
                unsigned u = __float_as_uint(v);
                if (v > 0.0f && (int)(u >> 21) == b1) {
                    int pos = atomicAdd(&s_m, 1);
                    cand[pos] = u;
                }
            }
            __syncthreads();
            #pragma unroll
            for (int h = tid; h < 2048; h += P1BT) hist[h] = 0;
            __syncthreads();
            for (int k = tid; k < m; k += P1BT)
                atomicAdd(&hist[(cand[k] >> 10) & 0x7FFu], 1u);
            __syncthreads();
            if (wid == 0) locate_warp(hist, 2048, want2, lane, &s_bin, &s_wrem);
            __syncthreads();
            b2 = s_bin; want3 = s_wrem;
            __syncthreads();
            #pragma unroll
            for (int h = tid; h < 1024; h += P1BT) hist[h] = 0;
            __syncthreads();
            for (int k = tid; k < m; k += P1BT)
                if ((int)((cand[k] >> 10) & 0x7FFu) == b2)
                    atomicAdd(&hist[cand[k] & 0x3FFu], 1u);
            __syncthreads();
            if (wid == 0) locate_warp(hist, 1024, want3, lane, &s_bin, &s_wrem);
            __syncthreads();
            b3 = s_bin;
        } else {
            #pragma unroll
            for (int h = tid; h < 2048; h += P1BT) hist[h] = 0;
            __syncthreads();
            for (int c = tid; c < cnt; c += P1BT) {
                float v = vbase[c];
                unsigned u = __float_as_uint(v);
                if (v > 0.0f && (int)(u >> 21) == b1)
                    atomicAdd(&hist[(u >> 10) & 0x7FFu], 1u);
            }
            __syncthreads();
            if (wid == 0) locate_warp(hist, 2048, want2, lane, &s_bin, &s_wrem);
            __syncthreads();
            b2 = s_bin; want3 = s_wrem;
            __syncthreads();
            unsigned pref21 = ((unsigned)b1 << 11) | (unsigned)b2;
            #pragma unroll
            for (int h = tid; h < 1024; h += P1BT) hist[h] = 0;
            __syncthreads();
            for (int c = tid; c < cnt; c += P1BT) {
                float v = vbase[c];
                unsigned u = __float_as_uint(v);
                if (v > 0.0f && (u >> 10) == pref21)
                    atomicAdd(&hist[u & 0x3FFu], 1u);
            }
            __syncthreads();
            if (wid == 0) locate_warp(hist, 1024, want3, lane, &s_bin, &s_wrem);
            __syncthreads();
            b3 = s_bin;
        }
        thr = __uint_as_float(((unsigned)b1 << 21) | ((unsigned)b2 << 10) | (unsigned)b3);
    }

    if (tid == 0) {
        g_thr[bn] = thr;
        g_lam[bn] = 1.0f / sqrtf((float)dk);
    }
}

// ---------------- Phase 2: per-pixel argmax/tie across boxes + outputs ----------------
__global__ __launch_bounds__(256) void phase2_kernel(
    const float* __restrict__ pred,  // [BS,4,H,W]
    float* __restrict__ out)         // cls [BS,H,W,3] then pts [BS,H,W,6]
{
    __shared__ unsigned s_mask[2];
    __shared__ int   s_ncand;
    __shared__ int   s_bxp[NBOX], s_byp[NBOX], s_clsid[NBOX];
    __shared__ float s_thr[NBOX], s_cx[NBOX], s_cy[NBOX], s_bw[NBOX], s_bh[NBOX];
    __shared__ float s_sc[NBOX], s_lm[NBOX];

    const int b = blockIdx.z;
    const int j0 = blockIdx.x * 64;
    const int i0 = blockIdx.y * 4;
    const int tid = threadIdx.x;

    bool f = false;
    int bxp = 0, byp = 0;
    if (tid < NBOX) {
        int idx = b * NBOX + tid;
        bxp = g_bx[idx]; byp = g_by[idx];
        int x0 = bxp & 0xFFFF, x1 = bxp >> 16;
        int y0 = byp & 0xFFFF, y1 = byp >> 16;
        f = (x0 <= j0 + 63) && (x1 >= j0) && (y0 <= i0 + 3) && (y1 >= i0);
    }
    unsigned m = __ballot_sync(0xFFFFFFFFu, f);
    if (tid < NBOX && (tid & 31) == 0) s_mask[tid >> 5] = m;
    __syncthreads();
    int base0 = __popc(s_mask[0]);
    if (tid == 0) s_ncand = base0 + __popc(s_mask[1]);
    if (f) {
        int lane = tid & 31;
        int pos = ((tid >> 5) ? base0 : 0) + __popc(m & ((1u << lane) - 1u));
        int idx = b * NBOX + tid;
        s_bxp[pos] = bxp; s_byp[pos] = byp;
        s_thr[pos] = g_thr[idx];
        s_cx[pos] = g_cx[idx]; s_cy[pos] = g_cy[idx];
        s_bw[pos] = g_bw[idx]; s_bh[pos] = g_bh[idx];
        s_sc[pos] = g_score[idx]; s_lm[pos] = g_lam[idx];
        s_clsid[pos] = g_cls[idx];
    }
    __syncthreads();

    const int j = j0 + (tid & 63);
    const int i = i0 + (tid >> 6);
    const int pix = i * WW + j;

    const float* pb = pred + (b * 4) * HW + pix;
    float p0 = pb[0 * HW], p1 = pb[1 * HW], p2 = pb[2 * HW], p3 = pb[3 * HW];
    float rx = __fmul_rn(__fadd_rn((float)j, 0.5f), 2.0f);
    float ry = __fmul_rn(__fadd_rn((float)i, 0.5f), 2.0f);
    PGeom g = pred_geom(p0, p1, p2, p3, rx, ry);

    float best = 0.0f;
    int win = 0;
    int cntmax = 0;
    bool inreg = false;
    const int nc = s_ncand;
    for (int k = 0; k < nc; k++) {
        int bp = s_bxp[k], yp = s_byp[k];
        if (j >= (bp & 0xFFFF) && j <= (bp >> 16) &&
            i >= (yp & 0xFFFF) && i <= (yp >> 16)) {
            inreg = true;
            float iou = iou_fn(g, s_cx[k], s_cy[k], s_bw[k], s_bh[k]);
            float kept = (iou > s_thr[k]) ? iou : 0.0f;
            if (kept > best) { best = kept; win = k; cntmax = 1; }
            else if (kept == best && kept > 0.0f) cntmax++;
        }
    }

    bool assigned = (best > 0.0f);
    float c0, c1, c2;
    if (assigned) {
        if (cntmax > 1) { c0 = c1 = c2 = 0.0f; }
        else {
            int ci = s_clsid[win];
            c0 = (ci == 0) ? 1.0f : 0.0f;
            c1 = (ci == 1) ? 1.0f : 0.0f;
            c2 = (ci == 2) ? 1.0f : 0.0f;
        }
    } else if (inreg) {
        c0 = c1 = c2 = 0.0f;
    } else {
        c0 = 1.0f; c1 = 0.0f; c2 = 0.0f;
    }
    int cidx = (b * HW + pix) * 3;
    out[cidx + 0] = c0; out[cidx + 1] = c1; out[cidx + 2] = c2;

    int pidx = BS * HW * 3 + (b * HW + pix) * 6;
    float2* pv = reinterpret_cast<float2*>(out + pidx);
    if (assigned) {
        pv[0] = make_float2(s_cx[win], s_cy[win]);
        pv[1] = make_float2(s_bw[win], s_bh[win]);
        pv[2] = make_float2(s_sc[win], s_lm[win]);
    } else {
        pv[0] = make_float2(1.0f, 1.0f);
        pv[1] = make_float2(1.0f, 1.0f);
        pv[2] = make_float2(1.0f, 1.0f);
    }
}

extern "C" void kernel_launch(void* const* d_in, const int* in_sizes, int n_in,
                              void* d_out, int out_size) {
    // inputs: [0]=feat (unused), [1]=pred, [2]=bboxes, [3]=difficult_mode (int32)
    const float* pred   = (const float*)d_in[1];
    const float* bboxes = (const float*)d_in[2];
    const int*   dmode  = (const int*)d_in[3];
    float* out = (float*)d_out;

    phase0_kernel<<<1, NB>>>(bboxes, dmode);
    dim3 g1a(NB, SPLIT);
    phase1a_kernel<<<g1a, P1AT>>>(pred);
    phase1b_kernel<<<NB, P1BT>>>();
    dim3 g2(WW / 64, HH / 4, BS);
    phase2_kernel<<<g2, 256>>>(pred, out);
}

// round 17
// speedup vs baseline: 1.1531x; 1.0344x over previous
#include <cuda_runtime.h>
#include <cuda_bf16.h>

#define MW_F 1280.0f
#define MH_F 768.0f
#define HH 384
#define WW 640
#define HW (HH*WW)
#define BS 4
#define NBOX 64
#define NB (BS*NBOX)
#define SCALE_F 80.0f
#define MAXRC 104
#define MAXCELLS (MAXRC*MAXRC)
#define P1BT 256
#define CANDMAX 2048

// IoU scratch (phase1a -> phase1b/phase2)
__device__ float g_vals[NB * MAXCELLS];     // ~11MB

// Per-box params (phase0) and results (phase1b) -> consumers
__device__ float g_thr[NB], g_cx[NB], g_cy[NB], g_bw[NB], g_bh[NB], g_score[NB], g_lam[NB];
__device__ int   g_bx[NB], g_by[NB], g_cls[NB], g_cnt[NB], g_rw[NB];

struct PGeom { float mnx, mxx, mny, mxy, pw, ph; };

__device__ __forceinline__ PGeom pred_geom(float p0, float p1, float p2, float p3,
                                           float rx, float ry) {
    float x1 = __fadd_rn(__fmul_rn(p0, SCALE_F), rx);
    float y1 = __fadd_rn(__fmul_rn(p1, SCALE_F), ry);
    float x2 = __fadd_rn(__fmul_rn(p2, SCALE_F), rx);
    float y2 = __fadd_rn(__fmul_rn(p3, SCALE_F), ry);
    float w  = __fsub_rn(x2, x1);
    float h  = __fsub_rn(y2, y1);
    float cx = __fadd_rn(x1, __fmul_rn(w, 0.5f));
    float cy = __fadd_rn(y1, __fmul_rn(h, 0.5f));
    PGeom g;
    g.mnx = __fsub_rn(cx, __fmul_rn(w, 0.5f));
    g.mxx = __fadd_rn(cx, __fmul_rn(w, 0.5f));
    g.mny = __fsub_rn(cy, __fmul_rn(h, 0.5f));
    g.mxy = __fadd_rn(cy, __fmul_rn(h, 0.5f));
    g.pw = w; g.ph = h;
    return g;
}

__device__ __forceinline__ float iou_fn(const PGeom& g, float cx, float cy,
                                        float bw, float bh) {
    float gmnx = __fsub_rn(cx, __fmul_rn(bw, 0.5f));
    float gmxx = __fadd_rn(cx, __fmul_rn(bw, 0.5f));
    float gmny = __fsub_rn(cy, __fmul_rn(bh, 0.5f));
    float gmxy = __fadd_rn(cy, __fmul_rn(bh, 0.5f));
    float iw = fmaxf(__fsub_rn(fminf(g.mxx, gmxx), fmaxf(g.mnx, gmnx)), 0.0f);
    float ih = fmaxf(__fsub_rn(fminf(g.mxy, gmxy), fmaxf(g.mny, gmny)), 0.0f);
    float inter = __fmul_rn(iw, ih);
    float uni = __fsub_rn(__fadd_rn(__fmul_rn(g.pw, g.ph), __fmul_rn(bw, bh)), inter);
    return __fdiv_rn(inter, fmaxf(uni, 1e-6f));
}

// ---------------- Phase 0: per-box geometry, computed once ----------------
__global__ __launch_bounds__(NB) void phase0_kernel(
    const float* __restrict__ bboxes,  // [BS,NBOX,6]
    const int*   __restrict__ dmode)
{
    const int bn = threadIdx.x;
    const float* bx = bboxes + bn * 6;
    float x1 = bx[0], y1 = bx[1], x2 = bx[2], y2 = bx[3], clsf = bx[4], diff = bx[5];
    float bw = __fsub_rn(x2, x1);
    float bh = __fsub_rn(y2, y1);
    float cx = __fadd_rn(x1, __fmul_rn(bw, 0.5f));
    float cy = __fadd_rn(y1, __fmul_rn(bh, 0.5f));
    bool valid = (__fmul_rn(bw, bh) != 0.0f);

    float mnw = floorf(fmaxf(__fsub_rn(__fdiv_rn(__fmul_rn(x1, (float)WW), MW_F), 0.5f), 0.0f));
    float mnh = floorf(fmaxf(__fsub_rn(__fdiv_rn(__fmul_rn(y1, (float)HH), MH_F), 0.5f), 0.0f));
    float mxw = ceilf (fminf(__fsub_rn(__fdiv_rn(__fmul_rn(x2, (float)WW), MW_F), 0.5f), (float)(WW - 1)));
    float mxh = ceilf (fminf(__fsub_rn(__fdiv_rn(__fmul_rn(y2, (float)HH), MH_F), 0.5f), (float)(HH - 1)));
    int ix0 = (int)mnw, ix1 = (int)mxw, iy0 = (int)mnh, iy1 = (int)mxh;
    bool empty = (!valid) || (ix1 < ix0) || (iy1 < iy0);
    int rw = empty ? 0 : (ix1 - ix0 + 1);
    int rh = empty ? 0 : (iy1 - iy0 + 1);
    int cnt = rw * rh;
    if (cnt > MAXCELLS) cnt = MAXCELLS;

    g_cx[bn] = cx; g_cy[bn] = cy; g_bw[bn] = bw; g_bh[bn] = bh;
    g_cls[bn] = (int)clsf + 1;
    int dm = *dmode;
    g_score[bn] = dm ? ((diff >= 0.625f) ? 1.0f : 0.0f) : 1.0f;
    g_cnt[bn] = cnt; g_rw[bn] = rw;
    if (empty) { g_bx[bn] = 0xFFFF; g_by[bn] = 0xFFFF; }
    else       { g_bx[bn] = ix0 | (ix1 << 16); g_by[bn] = iy0 | (iy1 << 16); }
}

// ---------------- Phase 1a: pixel-parallel IoU compute (phase2-shaped) ----------------
__global__ __launch_bounds__(256) void phase1a_kernel(
    const float* __restrict__ pred)    // [BS,4,H,W]
{
    __shared__ unsigned s_mask[2];
    __shared__ int   s_ncand;
    __shared__ int   s_bxp[NBOX], s_byp[NBOX], s_vb[NBOX], s_rw[NBOX];
    __shared__ float s_cx[NBOX], s_cy[NBOX], s_bw[NBOX], s_bh[NBOX];

    const int b = blockIdx.z;
    const int j0 = blockIdx.x * 64;
    const int i0 = blockIdx.y * 4;
    const int tid = threadIdx.x;

    bool f = false;
    int bxp = 0, byp = 0;
    if (tid < NBOX) {
        int idx = b * NBOX + tid;
        bxp = g_bx[idx]; byp = g_by[idx];
        int x0 = bxp & 0xFFFF, x1 = bxp >> 16;
        int y0 = byp & 0xFFFF, y1 = byp >> 16;
        f = (x0 <= j0 + 63) && (x1 >= j0) && (y0 <= i0 + 3) && (y1 >= i0);
    }
    unsigned m = __ballot_sync(0xFFFFFFFFu, f);
    if (tid < NBOX && (tid & 31) == 0) s_mask[tid >> 5] = m;
    __syncthreads();
    int base0 = __popc(s_mask[0]);
    if (tid == 0) s_ncand = base0 + __popc(s_mask[1]);
    if (f) {
        int lane = tid & 31;
        int pos = ((tid >> 5) ? base0 : 0) + __popc(m & ((1u << lane) - 1u));
        int idx = b * NBOX + tid;
        s_bxp[pos] = bxp; s_byp[pos] = byp;
        s_vb[pos] = idx * MAXCELLS;
        s_rw[pos] = g_rw[idx];
        s_cx[pos] = g_cx[idx]; s_cy[pos] = g_cy[idx];
        s_bw[pos] = g_bw[idx]; s_bh[pos] = g_bh[idx];
    }
    __syncthreads();

    const int nc = s_ncand;
    if (nc == 0) return;

    const int j = j0 + (tid & 63);
    const int i = i0 + (tid >> 6);
    const int pix = i * WW + j;

    const float* pb = pred + (b * 4) * HW + pix;
    float p0 = pb[0 * HW], p1 = pb[1 * HW], p2 = pb[2 * HW], p3 = pb[3 * HW];
    float rx = __fmul_rn(__fadd_rn((float)j, 0.5f), 2.0f);
    float ry = __fmul_rn(__fadd_rn((float)i, 0.5f), 2.0f);
    PGeom g = pred_geom(p0, p1, p2, p3, rx, ry);

    for (int k = 0; k < nc; k++) {
        int bp = s_bxp[k], yp = s_byp[k];
        int x0 = bp & 0xFFFF, x1 = bp >> 16;
        int y0 = yp & 0xFFFF, y1 = yp >> 16;
        if (j >= x0 && j <= x1 && i >= y0 && i <= y1) {
            float iou = iou_fn(g, s_cx[k], s_cy[k], s_bw[k], s_bh[k]);
            g_vals[s_vb[k] + (i - y0) * s_rw[k] + (j - x0)] = iou;
        }
    }
}

// Warp-0-only locate: find bin B with suffix(bins>B) <= want < suffix+hist[B].
__device__ __forceinline__ void locate_warp(const unsigned* hist, int nbins,
                                            int want, int lane,
                                            int* s_bin, int* s_wrem) {
    const int chunk = nbins >> 5;
    const int base = lane * chunk;
    unsigned partial = 0;
    #pragma unroll 8
    for (int k = 0; k < chunk; k++) partial += hist[base + k];
    unsigned suf = partial;
    #pragma unroll
    for (int s = 1; s < 32; s <<= 1) {
        unsigned v = __shfl_down_sync(0xFFFFFFFFu, suf, s);
        if (lane + s < 32) suf += v;
    }
    unsigned running = suf - partial;
    for (int k = chunk - 1; k >= 0; k--) {
        unsigned h = hist[base + k];
        if ((unsigned)want >= running && (unsigned)want < running + h) {
            *s_bin = base + k;
            *s_wrem = (int)((unsigned)want - running);
        }
        running += h;
    }
}

// ---------------- Phase 1b: sum/count + exact rank-dk threshold ----------------
__global__ __launch_bounds__(P1BT) void phase1b_kernel()
{
    __shared__ unsigned hist[2048];
    __shared__ unsigned cand[CANDMAX];
    __shared__ float s_wsum[8];
    __shared__ int   s_wcnt[8];
    __shared__ int s_dk, s_P, s_bin, s_wrem, s_m;

    const int bn = blockIdx.x;
    const int tid = threadIdx.x;
    const int lane = tid & 31;
    const int wid = tid >> 5;

    const float* vbase = g_vals + bn * MAXCELLS;
    const int cnt = g_cnt[bn];

    // fused pass: sum + positive count + level-1 histogram (bits [31:21])
    #pragma unroll
    for (int h = tid; h < 2048; h += P1BT) hist[h] = 0;
    if (tid == 0) s_m = 0;
    __syncthreads();

    float psum = 0.0f;
    int pcount = 0;
    for (int c = tid; c < cnt; c += P1BT) {
        float v = vbase[c];
        if (v > 0.0f) {
            psum += v; pcount++;
            atomicAdd(&hist[__float_as_uint(v) >> 21], 1u);
        }
    }
    #pragma unroll
    for (int off = 16; off > 0; off >>= 1) {
        psum += __shfl_down_sync(0xFFFFFFFFu, psum, off);
        pcount += __shfl_down_sync(0xFFFFFFFFu, pcount, off);
    }
    if (lane == 0) { s_wsum[wid] = psum; s_wcnt[wid] = pcount; }
    __syncthreads();
    if (tid == 0) {
        float t = 0.0f; int p = 0;
        #pragma unroll
        for (int w = 0; w < 8; w++) { t += s_wsum[w]; p += s_wcnt[w]; }
        float dkf = ceilf(fmaxf(t, 1.0f));
        if (!(dkf < (float)(HW - 1))) dkf = (float)(HW - 1);
        s_dk = (int)dkf;
        s_P = p;
    }
    __syncthreads();

    const int dk = s_dk;
    const int P = s_P;
    float thr = 0.0f;

    if (dk < P) {
        if (wid == 0) locate_warp(hist, 2048, dk, lane, &s_bin, &s_wrem);
        __syncthreads();
        const int b1 = s_bin, want2 = s_wrem;
        const int m = (int)hist[b1];
        __syncthreads();

        int b2, b3, want3;
        if (m <= CANDMAX) {
            for (int c = tid; c < cnt; c += P1BT) {
                float v = vbase[c];
                unsigned u = __float_as_uint(v);
                if (v > 0.0f && (int)(u >> 21) == b1) {
                    int pos = atomicAdd(&s_m, 1);
                    cand[pos] = u;
                }
            }
            __syncthreads();
            #pragma unroll
            for (int h = tid; h < 2048; h += P1BT) hist[h] = 0;
            __syncthreads();
            for (int k = tid; k < m; k += P1BT)
                atomicAdd(&hist[(cand[k] >> 10) & 0x7FFu], 1u);
            __syncthreads();
            if (wid == 0) locate_warp(hist, 2048, want2, lane, &s_bin, &s_wrem);
            __syncthreads();
            b2 = s_bin; want3 = s_wrem;
            __syncthreads();
            #pragma unroll
            for (int h = tid; h < 1024; h += P1BT) hist[h] = 0;
            __syncthreads();
            for (int k = tid; k < m; k += P1BT)
                if ((int)((cand[k] >> 10) & 0x7FFu) == b2)
                    atomicAdd(&hist[cand[k] & 0x3FFu], 1u);
            __syncthreads();
            if (wid == 0) locate_warp(hist, 1024, want3, lane, &s_bin, &s_wrem);
            __syncthreads();
            b3 = s_bin;
        } else {
            #pragma unroll
            for (int h = tid; h < 2048; h += P1BT) hist[h] = 0;
            __syncthreads();
            for (int c = tid; c < cnt; c += P1BT) {
                float v = vbase[c];
                unsigned u = __float_as_uint(v);
                if (v > 0.0f && (int)(u >> 21) == b1)
                    atomicAdd(&hist[(u >> 10) & 0x7FFu], 1u);
            }
            __syncthreads();
            if (wid == 0) locate_warp(hist, 2048, want2, lane, &s_bin, &s_wrem);
            __syncthreads();
            b2 = s_bin; want3 = s_wrem;
            __syncthreads();
            unsigned pref21 = ((unsigned)b1 << 11) | (unsigned)b2;
            #pragma unroll
            for (int h = tid; h < 1024; h += P1BT) hist[h] = 0;
            __syncthreads();
            for (int c = tid; c < cnt; c += P1BT) {
                float v = vbase[c];
                unsigned u = __float_as_uint(v);
                if (v > 0.0f && (u >> 10) == pref21)
                    atomicAdd(&hist[u & 0x3FFu], 1u);
            }
            __syncthreads();
            if (wid == 0) locate_warp(hist, 1024, want3, lane, &s_bin, &s_wrem);
            __syncthreads();
            b3 = s_bin;
        }
        thr = __uint_as_float(((unsigned)b1 << 21) | ((unsigned)b2 << 10) | (unsigned)b3);
    }

    if (tid == 0) {
        g_thr[bn] = thr;
        g_lam[bn] = 1.0f / sqrtf((float)dk);
    }
}

// ---------------- Phase 2: per-pixel argmax/tie, IoU read from g_vals ----------------
__global__ __launch_bounds__(256) void phase2_kernel(
    float* __restrict__ out)         // cls [BS,H,W,3] then pts [BS,H,W,6]
{
    __shared__ unsigned s_mask[2];
    __shared__ int   s_ncand;
    __shared__ int   s_bxp[NBOX], s_byp[NBOX], s_clsid[NBOX], s_vb[NBOX], s_rw[NBOX];
    __shared__ float s_thr[NBOX], s_cx[NBOX], s_cy[NBOX], s_bw[NBOX], s_bh[NBOX];
    __shared__ float s_sc[NBOX], s_lm[NBOX];

    const int b = blockIdx.z;
    const int j0 = blockIdx.x * 64;
    const int i0 = blockIdx.y * 4;
    const int tid = threadIdx.x;

    bool f = false;
    int bxp = 0, byp = 0;
    if (tid < NBOX) {
        int idx = b * NBOX + tid;
        bxp = g_bx[idx]; byp = g_by[idx];
        int x0 = bxp & 0xFFFF, x1 = bxp >> 16;
        int y0 = byp & 0xFFFF, y1 = byp >> 16;
        f = (x0 <= j0 + 63) && (x1 >= j0) && (y0 <= i0 + 3) && (y1 >= i0);
    }
    unsigned m = __ballot_sync(0xFFFFFFFFu, f);
    if (tid < NBOX && (tid & 31) == 0) s_mask[tid >> 5] = m;
    __syncthreads();
    int base0 = __popc(s_mask[0]);
    if (tid == 0) s_ncand = base0 + __popc(s_mask[1]);
    if (f) {
        int lane = tid & 31;
        int pos = ((tid >> 5) ? base0 : 0) + __popc(m & ((1u << lane) - 1u));
        int idx = b * NBOX + tid;
        s_bxp[pos] = bxp; s_byp[pos] = byp;
        s_vb[pos] = idx * MAXCELLS;
        s_rw[pos] = g_rw[idx];
        s_thr[pos] = g_thr[idx];
        s_cx[pos] = g_cx[idx]; s_cy[pos] = g_cy[idx];
        s_bw[pos] = g_bw[idx]; s_bh[pos] = g_bh[idx];
        s_sc[pos] = g_score[idx]; s_lm[pos] = g_lam[idx];
        s_clsid[pos] = g_cls[idx];
    }
    __syncthreads();

    const int j = j0 + (tid & 63);
    const int i = i0 + (tid >> 6);
    const int pix = i * WW + j;

    float best = 0.0f;
    int win = 0;
    int cntmax = 0;
    bool inreg = false;
    const int nc = s_ncand;
    for (int k = 0; k < nc; k++) {
        int bp = s_bxp[k], yp = s_byp[k];
        int x0 = bp & 0xFFFF, x1 = bp >> 16;
        int y0 = yp & 0xFFFF, y1 = yp >> 16;
        if (j >= x0 && j <= x1 && i >= y0 && i <= y1) {
            inreg = true;
            float iou = g_vals[s_vb[k] + (i - y0) * s_rw[k] + (j - x0)];
            float kept = (iou > s_thr[k]) ? iou : 0.0f;
            if (kept > best) { best = kept; win = k; cntmax = 1; }
            else if (kept == best && kept > 0.0f) cntmax++;
        }
    }

    bool assigned = (best > 0.0f);
    float c0, c1, c2;
    if (assigned) {
        if (cntmax > 1) { c0 = c1 = c2 = 0.0f; }
        else {
            int ci = s_clsid[win];
            c0 = (ci == 0) ? 1.0f : 0.0f;
            c1 = (ci == 1) ? 1.0f : 0.0f;
            c2 = (ci == 2) ? 1.0f : 0.0f;
        }
    } else if (inreg) {
        c0 = c1 = c2 = 0.0f;
    } else {
        c0 = 1.0f; c1 = 0.0f; c2 = 0.0f;
    }
    int cidx = (b * HW + pix) * 3;
    out[cidx + 0] = c0; out[cidx + 1] = c1; out[cidx + 2] = c2;

    int pidx = BS * HW * 3 + (b * HW + pix) * 6;
    float2* pv = reinterpret_cast<float2*>(out + pidx);
    if (assigned) {
        pv[0] = make_float2(s_cx[win], s_cy[win]);
        pv[1] = make_float2(s_bw[win], s_bh[win]);
        pv[2] = make_float2(s_sc[win], s_lm[win]);
    } else {
        pv[0] = make_float2(1.0f, 1.0f);
        pv[1] = make_float2(1.0f, 1.0f);
        pv[2] = make_float2(1.0f, 1.0f);
    }
}

extern "C" void kernel_launch(void* const* d_in, const int* in_sizes, int n_in,
                              void* d_out, int out_size) {
    // inputs: [0]=feat (unused), [1]=pred, [2]=bboxes, [3]=difficult_mode (int32)
    const float* pred   = (const float*)d_in[1];
    const float* bboxes = (const float*)d_in[2];
    const int*   dmode  = (const int*)d_in[3];
    float* out = (float*)d_out;

    phase0_kernel<<<1, NB>>>(bboxes, dmode);
    dim3 g1(WW / 64, HH / 4, BS);
    phase1a_kernel<<<g1, 256>>>(pred);
    phase1b_kernel<<<NB, P1BT>>>();
    phase2_kernel<<<g1, 256>>>(out);
}